// round 1
// baseline (speedup 1.0000x reference)
#include <cuda_runtime.h>
#include <cuda_bf16.h>
#include <math.h>

// Problem constants (fixed by reference: N_O=64, N_H=128; sizes derived at launch)
#define NO 64
#define NH 128
#define N_MAX 192
#define NB_MAX 600

// Scratch (allocation-free per harness rules): per-frame histograms for
// R*3 pair-types * T frames * nb bins = 8*3*100*600 = 1,440,000 floats.
__device__ float g_hists[1600000];
__device__ float g_maes[32 * 3];
__device__ int g_idxO[NO];
__device__ int g_idxH[NH];

// ---------------------------------------------------------------------------
// Build O/H index lists from ptypes (matches jnp.nonzero(size=K) incl. 0-fill)
// ---------------------------------------------------------------------------
__global__ void setup_idx_kernel(const int* __restrict__ ptypes, int N) {
    if (blockIdx.x == 0 && threadIdx.x == 0) {
        int no = 0, nh = 0;
        for (int i = 0; i < N; i++) {
            int t = ptypes[i];
            if (t == 8 && no < NO) g_idxO[no++] = i;
            if (t == 1 && nh < NH) g_idxH[nh++] = i;
        }
        for (; no < NO; no++) g_idxO[no] = 0;
        for (; nh < NH; nh++) g_idxH[nh] = 0;
    }
}

// ---------------------------------------------------------------------------
// Per-(replica, pair-type, frame) all-pairs distance histogram.
// blockIdx.x = (r*3 + p)*T + t
// ---------------------------------------------------------------------------
__global__ __launch_bounds__(256) void hist_kernel(
    const float* __restrict__ radii,   // (T, R, N, 3)
    const float* __restrict__ lat,     // (3,)
    const float* __restrict__ bins,    // (nb+1,)
    int T, int R, int N, int nb)
{
    __shared__ float sx[N_MAX * 3];
    __shared__ float bins_s[NB_MAX + 1];
    __shared__ int hist[NB_MAX];
    __shared__ int idxO_s[NO];
    __shared__ int idxH_s[NH];

    const int bid = blockIdx.x;
    const int t  = bid % T;
    const int rp = bid / T;
    const int p  = rp % 3;
    const int r  = rp / 3;
    const int tid = threadIdx.x;

    const float L0 = lat[0], L1 = lat[1], L2 = lat[2];

    // Load + wrap coordinates: w = (x/L - floor(x/L)) * L  (matches x/L % 1 * L)
    const float* base = radii + ((size_t)t * R + r) * (size_t)N * 3;
    for (int i = tid; i < N; i += blockDim.x) {
        float f;
        f = base[3*i    ] / L0; sx[3*i    ] = (f - floorf(f)) * L0;
        f = base[3*i + 1] / L1; sx[3*i + 1] = (f - floorf(f)) * L1;
        f = base[3*i + 2] / L2; sx[3*i + 2] = (f - floorf(f)) * L2;
    }
    for (int i = tid; i <= nb; i += blockDim.x) bins_s[i] = bins[i];
    for (int i = tid; i < nb; i += blockDim.x) hist[i] = 0;
    for (int i = tid; i < NO; i += blockDim.x) idxO_s[i] = g_idxO[i];
    for (int i = tid; i < NH; i += blockDim.x) idxH_s[i] = g_idxH[i];
    __syncthreads();

    // p=0: OO (64x64), p=1: HH (128x128), p=2: HO (idx0=H n0=128, idx1=O n1=64)
    const int* ia = (p == 0) ? idxO_s : idxH_s;
    const int* ib = (p == 1) ? idxH_s : idxO_s;
    const int n0 = (p == 0) ? NO : NH;
    const int n1 = (p == 1) ? NH : NO;

    const float b0 = bins_s[0], bN = bins_s[nb];
    const float inv_dx = (float)nb / (bN - b0);
    const float h0 = 0.5f * L0, h1 = 0.5f * L1, h2 = 0.5f * L2;

    const int npairs = n0 * n1;
    for (int q = tid; q < npairs; q += blockDim.x) {
        const int i = q / n1;
        const int j = q - i * n1;   // j varies fastest (stride-3 smem, conflict-free)
        const float* A = &sx[3 * ia[i]];
        const float* B = &sx[3 * ib[j]];
        float dx = fabsf(A[0] - B[0]); if (dx > h0) dx -= L0;
        float dy = fabsf(A[1] - B[1]); if (dy > h1) dy -= L1;
        float dz = fabsf(A[2] - B[2]); if (dz > h2) dz -= L2;
        const float s = dx * dx + dy * dy + dz * dz;
        const float d = sqrtf(s);
        if (d < b0 || d > bN) continue;      // weight = (d>=b0)&(d<=bN); d=0 self-pairs drop
        int k = (int)((d - b0) * inv_dx);
        if (k > nb - 1) k = nb - 1;
        if (k < 0) k = 0;
        // exact searchsorted('right')-1 semantics against real bin edges
        while (k < nb - 1 && bins_s[k + 1] <= d) k++;
        while (k > 0 && bins_s[k] > d) k--;
        atomicAdd(&hist[k], 1);
    }
    __syncthreads();

    float* gh = g_hists + ((size_t)(r * 3 + p) * T + t) * nb;
    for (int i = tid; i < nb; i += blockDim.x) gh[i] = (float)hist[i];
}

// ---------------------------------------------------------------------------
// Per-(replica, pair-type) normalization + rdf + MAE.
// rdf[b] = (S/T) * sum_t h[t,b] / (shell_b * u_t),  u_t = sum_b h[t,b]/shell_b
// S = (vol/(T*P)) * sum_b H_b/shell_b
// ---------------------------------------------------------------------------
__global__ __launch_bounds__(256) void reduce_kernel(
    const float* __restrict__ bins,
    const float* __restrict__ lat,
    const float* __restrict__ gt_oo,
    const float* __restrict__ gt_hh,
    const float* __restrict__ gt_ho,
    float* __restrict__ out,
    int T, int nb, int R)
{
    __shared__ float shell[NB_MAX];
    __shared__ float u[256];
    __shared__ float red[256];

    const int bidx = blockIdx.x;
    const int p = bidx % 3;
    const int r = bidx / 3;
    const int tid = threadIdx.x;

    const float c = (float)(4.0 / 3.0 * M_PI);
    for (int b = tid; b < nb; b += blockDim.x) {
        const float lo = bins[b], hi = bins[b + 1];
        shell[b] = c * (hi * hi * hi - lo * lo * lo);
    }
    __syncthreads();

    const float* H = g_hists + (size_t)(r * 3 + p) * T * nb;

    // per-frame weights u_t
    for (int t = tid; t < T; t += blockDim.x) {
        float acc = 0.0f;
        const float* row = H + (size_t)t * nb;
        for (int b = 0; b < nb; b++) acc += row[b] / shell[b];
        u[t] = acc;
    }
    __syncthreads();

    // per-bin numerators + total-count sum for S
    float numb[3];                 // ceil(600/256) = 3 bins per thread
    float myHsum = 0.0f;
    for (int b = tid, k = 0; b < nb; b += blockDim.x, k++) {
        float Hb = 0.0f, num = 0.0f;
        for (int t = 0; t < T; t++) {
            const float h = H[(size_t)t * nb + b];
            Hb  += h;
            num += h / u[t];
        }
        numb[k] = num;
        myHsum += Hb / shell[b];
    }
    red[tid] = myHsum;
    __syncthreads();
    for (int s = 128; s > 0; s >>= 1) {
        if (tid < s && tid + s < blockDim.x) red[tid] += red[tid + s];
        __syncthreads();
    }
    const float sumHb = red[0];
    __syncthreads();

    const float vol = lat[0] * lat[1] * lat[2];
    const int P = (p == 0) ? NO * NO : (p == 1) ? NH * NH : NH * NO;
    const float S = vol / ((float)T * (float)P) * sumHb;
    const float invT = 1.0f / (float)T;
    const float* gt = (p == 0) ? gt_oo : (p == 1) ? gt_hh : gt_ho;

    float* ro = out + ((size_t)r * 3 + p) * nb;
    float myabs = 0.0f;
    for (int b = tid, k = 0; b < nb; b += blockDim.x, k++) {
        const float rdf = S * invT * numb[k] / shell[b];
        ro[b] = rdf;
        myabs += fabsf(rdf - gt[b]);
    }
    red[tid] = myabs;
    __syncthreads();
    for (int s = 128; s > 0; s >>= 1) {
        if (tid < s && tid + s < blockDim.x) red[tid] += red[tid + s];
        __syncthreads();
    }
    if (tid == 0) g_maes[r * 3 + p] = 6.0f * red[0] / (float)nb;  // XLIM * mean
}

__global__ void mae_max_kernel(float* __restrict__ out, int R, int nb) {
    const int r = threadIdx.x;
    if (r < R) {
        float m = g_maes[r * 3];
        m = fmaxf(m, g_maes[r * 3 + 1]);
        m = fmaxf(m, g_maes[r * 3 + 2]);
        out[(size_t)R * 3 * nb + r] = m;
    }
}

// ---------------------------------------------------------------------------
extern "C" void kernel_launch(void* const* d_in, const int* in_sizes, int n_in,
                              void* d_out, int out_size) {
    const float* radii = (const float*)d_in[0];   // (T,R,N,3)
    const int*   ptypes = (const int*)d_in[1];    // (N,)
    const float* lat   = (const float*)d_in[2];   // (3,)
    const float* bins  = (const float*)d_in[3];   // (nb+1,)
    const float* gt_oo = (const float*)d_in[4];
    const float* gt_hh = (const float*)d_in[5];
    const float* gt_ho = (const float*)d_in[6];
    float* out = (float*)d_out;

    const int nb = in_sizes[3] - 1;                    // 600
    const int N  = in_sizes[1];                        // 192
    const int R  = out_size / (3 * nb + 1);            // 8  (out = R*3*nb rdf + R maes)
    const int T  = in_sizes[0] / (R * N * 3);          // 100

    setup_idx_kernel<<<1, 1>>>(ptypes, N);
    hist_kernel<<<R * 3 * T, 256>>>(radii, lat, bins, T, R, N, nb);
    reduce_kernel<<<R * 3, 256>>>(bins, lat, gt_oo, gt_hh, gt_ho, out, T, nb, R);
    mae_max_kernel<<<1, 32>>>(out, R, nb);
}

// round 2
// speedup vs baseline: 1.1160x; 1.1160x over previous
#include <cuda_runtime.h>
#include <cuda_bf16.h>
#include <math.h>

#define NO 64
#define NH 128
#define N_MAX 192
#define NB_MAX 600

// Scratch (allocation-free): per-frame histograms R*3*T*nb = 1,440,000 floats.
__device__ float g_hists[1600000];
__device__ float g_maes[32 * 3];
__device__ int g_idxO[NO];
__device__ int g_idxH[NH];

// ---------------------------------------------------------------------------
__global__ void setup_idx_kernel(const int* __restrict__ ptypes, int N) {
    if (blockIdx.x == 0 && threadIdx.x == 0) {
        int no = 0, nh = 0;
        for (int i = 0; i < N; i++) {
            int t = ptypes[i];
            if (t == 8 && no < NO) g_idxO[no++] = i;
            if (t == 1 && nh < NH) g_idxH[nh++] = i;
        }
        for (; no < NO; no++) g_idxO[no] = 0;
        for (; nh < NH; nh++) g_idxH[nh] = 0;
    }
}

// ---------------------------------------------------------------------------
// Pair -> histogram bin -> shared atomic. Arithmetic identical to Round 1.
// ---------------------------------------------------------------------------
__device__ __forceinline__ void do_pair(
    const float4 A, const float4 B,
    const float L0, const float L1, const float L2,
    const float h0, const float h1, const float h2,
    const float b0, const float bN, const float inv_dx, const int nb,
    const float* __restrict__ bins_s, int* __restrict__ hist, const int w)
{
    float dx = fabsf(A.x - B.x); if (dx > h0) dx -= L0;
    float dy = fabsf(A.y - B.y); if (dy > h1) dy -= L1;
    float dz = fabsf(A.z - B.z); if (dz > h2) dz -= L2;
    const float s = dx * dx + dy * dy + dz * dz;
    const float d = sqrtf(s);
    if (d >= b0 && d <= bN) {
        int k = (int)((d - b0) * inv_dx);
        if (k > nb - 1) k = nb - 1;
        if (k < 0) k = 0;
        // uniform-map error << bin width: at most one-step correction needed
        if (k < nb - 1 && bins_s[k + 1] <= d) k++;
        else if (k > 0 && bins_s[k] > d) k--;
        atomicAdd(&hist[k], w);
    }
}

// ---------------------------------------------------------------------------
// Per-(replica, pair-type, frame) histogram. blockIdx.x = (r*3+p)*T + t
// Symmetric pair types (OO, HH) enumerate each unordered pair ONCE via
// balanced round-robin offsets, with weight 2 (weight 1 at the half-offset,
// where each pair is generated twice) -> bitwise-identical counts, ~half the
// shared atomics.
// ---------------------------------------------------------------------------
__global__ __launch_bounds__(256) void hist_kernel(
    const float* __restrict__ radii,   // (T, R, N, 3)
    const float* __restrict__ lat,     // (3,)
    const float* __restrict__ bins,    // (nb+1,)
    int T, int R, int N, int nb)
{
    __shared__ float4 sO[NO];
    __shared__ float4 sH[NH];
    __shared__ float bins_s[NB_MAX + 1];
    __shared__ int hist[NB_MAX];

    const int bid = blockIdx.x;
    const int t  = bid % T;
    const int rp = bid / T;
    const int p  = rp % 3;
    const int r  = rp / 3;
    const int tid = threadIdx.x;

    const float L0 = lat[0], L1 = lat[1], L2 = lat[2];

    // Gather + wrap: w = (x/L - floor(x/L)) * L
    const float* base = radii + ((size_t)t * R + r) * (size_t)N * 3;
    for (int i = tid; i < NO; i += blockDim.x) {
        const int g = g_idxO[i];
        float f0 = base[3 * g    ] / L0;
        float f1 = base[3 * g + 1] / L1;
        float f2 = base[3 * g + 2] / L2;
        sO[i] = make_float4((f0 - floorf(f0)) * L0,
                            (f1 - floorf(f1)) * L1,
                            (f2 - floorf(f2)) * L2, 0.0f);
    }
    for (int i = tid; i < NH; i += blockDim.x) {
        const int g = g_idxH[i];
        float f0 = base[3 * g    ] / L0;
        float f1 = base[3 * g + 1] / L1;
        float f2 = base[3 * g + 2] / L2;
        sH[i] = make_float4((f0 - floorf(f0)) * L0,
                            (f1 - floorf(f1)) * L1,
                            (f2 - floorf(f2)) * L2, 0.0f);
    }
    for (int i = tid; i <= nb; i += blockDim.x) bins_s[i] = bins[i];
    for (int i = tid; i < nb; i += blockDim.x) hist[i] = 0;
    __syncthreads();

    const float b0 = bins_s[0], bN = bins_s[nb];
    const float inv_dx = (float)nb / (bN - b0);
    const float h0 = 0.5f * L0, h1 = 0.5f * L1, h2 = 0.5f * L2;

    if (p < 2) {
        // symmetric: OO (n=64) or HH (n=128)
        const float4* arr = (p == 0) ? sO : sH;
        const int n    = (p == 0) ? NO : NH;
        const int step = 256 / n;                  // threads sharing one j
        const int j    = tid & (n - 1);
        const int c0   = tid / n;                  // 0..step-1
        const int half = n >> 1;
        const float4 B = arr[j];
        #pragma unroll 4
        for (int o = 1 + c0; o <= half; o += step) {
            const int i = (j + o) & (n - 1);
            const int w = (o == half) ? 1 : 2;
            do_pair(arr[i], B, L0, L1, L2, h0, h1, h2, b0, bN, inv_dx, nb,
                    bins_s, hist, w);
        }
    } else {
        // HO: all 128x64 pairs, weight 1
        const int j  = tid & (NO - 1);             // O point
        const int c0 = tid >> 6;                   // 0..3
        const float4 B = sO[j];
        #pragma unroll 4
        for (int i = c0; i < NH; i += 4) {
            do_pair(sH[i], B, L0, L1, L2, h0, h1, h2, b0, bN, inv_dx, nb,
                    bins_s, hist, 1);
        }
    }
    __syncthreads();

    float* gh = g_hists + ((size_t)(r * 3 + p) * T + t) * nb;
    for (int i = tid; i < nb; i += blockDim.x) gh[i] = (float)hist[i];
}

// ---------------------------------------------------------------------------
// Per-(replica, pair-type) normalization + rdf + MAE.
// rdf[b] = (S/T) * sum_t h[t,b] / (shell_b * u_t),  u_t = sum_b h[t,b]/shell_b
// S = (vol/(T*P)) * sum_b H_b/shell_b
// ---------------------------------------------------------------------------
__global__ __launch_bounds__(256) void reduce_kernel(
    const float* __restrict__ bins,
    const float* __restrict__ lat,
    const float* __restrict__ gt_oo,
    const float* __restrict__ gt_hh,
    const float* __restrict__ gt_ho,
    float* __restrict__ out,
    int T, int nb, int R)
{
    __shared__ float shell[NB_MAX];
    __shared__ float u[256];
    __shared__ float red[256];

    const int bidx = blockIdx.x;
    const int p = bidx % 3;
    const int r = bidx / 3;
    const int tid = threadIdx.x;

    const float c = (float)(4.0 / 3.0 * M_PI);
    for (int b = tid; b < nb; b += blockDim.x) {
        const float lo = bins[b], hi = bins[b + 1];
        shell[b] = c * (hi * hi * hi - lo * lo * lo);
    }
    __syncthreads();

    const float* H = g_hists + (size_t)(r * 3 + p) * T * nb;

    for (int t = tid; t < T; t += blockDim.x) {
        float acc = 0.0f;
        const float* row = H + (size_t)t * nb;
        for (int b = 0; b < nb; b++) acc += row[b] / shell[b];
        u[t] = acc;
    }
    __syncthreads();

    float numb[3];
    float myHsum = 0.0f;
    for (int b = tid, k = 0; b < nb; b += blockDim.x, k++) {
        float Hb = 0.0f, num = 0.0f;
        for (int t = 0; t < T; t++) {
            const float h = H[(size_t)t * nb + b];
            Hb  += h;
            num += h / u[t];
        }
        numb[k] = num;
        myHsum += Hb / shell[b];
    }
    red[tid] = myHsum;
    __syncthreads();
    for (int s = 128; s > 0; s >>= 1) {
        if (tid < s && tid + s < blockDim.x) red[tid] += red[tid + s];
        __syncthreads();
    }
    const float sumHb = red[0];
    __syncthreads();

    const float vol = lat[0] * lat[1] * lat[2];
    const int P = (p == 0) ? NO * NO : (p == 1) ? NH * NH : NH * NO;
    const float S = vol / ((float)T * (float)P) * sumHb;
    const float invT = 1.0f / (float)T;
    const float* gt = (p == 0) ? gt_oo : (p == 1) ? gt_hh : gt_ho;

    float* ro = out + ((size_t)r * 3 + p) * nb;
    float myabs = 0.0f;
    for (int b = tid, k = 0; b < nb; b += blockDim.x, k++) {
        const float rdf = S * invT * numb[k] / shell[b];
        ro[b] = rdf;
        myabs += fabsf(rdf - gt[b]);
    }
    red[tid] = myabs;
    __syncthreads();
    for (int s = 128; s > 0; s >>= 1) {
        if (tid < s && tid + s < blockDim.x) red[tid] += red[tid + s];
        __syncthreads();
    }
    if (tid == 0) g_maes[r * 3 + p] = 6.0f * red[0] / (float)nb;
}

__global__ void mae_max_kernel(float* __restrict__ out, int R, int nb) {
    const int r = threadIdx.x;
    if (r < R) {
        float m = g_maes[r * 3];
        m = fmaxf(m, g_maes[r * 3 + 1]);
        m = fmaxf(m, g_maes[r * 3 + 2]);
        out[(size_t)R * 3 * nb + r] = m;
    }
}

// ---------------------------------------------------------------------------
extern "C" void kernel_launch(void* const* d_in, const int* in_sizes, int n_in,
                              void* d_out, int out_size) {
    const float* radii  = (const float*)d_in[0];   // (T,R,N,3)
    const int*   ptypes = (const int*)d_in[1];     // (N,)
    const float* lat    = (const float*)d_in[2];   // (3,)
    const float* bins   = (const float*)d_in[3];   // (nb+1,)
    const float* gt_oo  = (const float*)d_in[4];
    const float* gt_hh  = (const float*)d_in[5];
    const float* gt_ho  = (const float*)d_in[6];
    float* out = (float*)d_out;

    const int nb = in_sizes[3] - 1;                 // 600
    const int N  = in_sizes[1];                     // 192
    const int R  = out_size / (3 * nb + 1);         // 8
    const int T  = in_sizes[0] / (R * N * 3);       // 100

    setup_idx_kernel<<<1, 1>>>(ptypes, N);
    hist_kernel<<<R * 3 * T, 256>>>(radii, lat, bins, T, R, N, nb);
    reduce_kernel<<<R * 3, 256>>>(bins, lat, gt_oo, gt_hh, gt_ho, out, T, nb, R);
    mae_max_kernel<<<1, 32>>>(out, R, nb);
}

// round 3
// speedup vs baseline: 3.1851x; 2.8541x over previous
#include <cuda_runtime.h>
#include <cuda_bf16.h>
#include <math.h>

#define NO 64
#define NH 128
#define NB_MAX 600

// Scratch (allocation-free): per-frame histograms R*3*T*nb = 1,440,000 floats.
__device__ float g_hists[1600000];
__device__ float g_maes[32 * 3];
__device__ float g_inv_shell[NB_MAX];
__device__ int g_idxO[NO];
__device__ int g_idxH[NH];
__device__ unsigned g_cnt;   // monotonic completion counter (never reset)

// ---------------------------------------------------------------------------
// init: ballot-compaction of O/H index lists + reciprocal shell volumes.
// grid=1, block=256.
// ---------------------------------------------------------------------------
__global__ __launch_bounds__(256) void init_kernel(
    const int* __restrict__ ptypes, const float* __restrict__ bins,
    int N, int nb)
{
    __shared__ int cntO[8], cntH[8], offO[8], offH[8];
    __shared__ int totO_s, totH_s;
    const int tid = threadIdx.x;
    const int wid = tid >> 5, lane = tid & 31;

    const int ty = (tid < N) ? ptypes[tid] : -1;
    const unsigned mO = __ballot_sync(0xffffffffu, ty == 8);
    const unsigned mH = __ballot_sync(0xffffffffu, ty == 1);
    if (lane == 0) { cntO[wid] = __popc(mO); cntH[wid] = __popc(mH); }
    __syncthreads();
    if (tid == 0) {
        int aO = 0, aH = 0;
        for (int w = 0; w < 8; w++) {
            offO[w] = aO; aO += cntO[w];
            offH[w] = aH; aH += cntH[w];
        }
        totO_s = aO; totH_s = aH;
    }
    __syncthreads();
    const unsigned lt = (1u << lane) - 1u;
    if (ty == 8) { int pos = offO[wid] + __popc(mO & lt); if (pos < NO) g_idxO[pos] = tid; }
    if (ty == 1) { int pos = offH[wid] + __popc(mH & lt); if (pos < NH) g_idxH[pos] = tid; }
    for (int j = totO_s + tid; j < NO; j += 256) g_idxO[j] = 0;
    for (int j = totH_s + tid; j < NH; j += 256) g_idxH[j] = 0;

    const float c = (float)(4.0 / 3.0 * M_PI);
    for (int b = tid; b < nb; b += 256) {
        const float lo = bins[b], hi = bins[b + 1];
        g_inv_shell[b] = 1.0f / (c * (hi * hi * hi - lo * lo * lo));
    }
}

// ---------------------------------------------------------------------------
// Branchless pair visit: min-image distance -> bin -> predicated shared red.
// No C-level if{} anywhere -> no BSSY/BSYNC in the inner loop.
// ---------------------------------------------------------------------------
__device__ __forceinline__ void do_pair(
    const float4 A, const float4 B,
    const float L0, const float L1, const float L2,
    const float b0, const float bN, const float inv_dx, const float kc,
    const int nbm1, const float* __restrict__ bins_s,
    const unsigned hbase, const int w)
{
    float dx = fabsf(A.x - B.x); dx = fminf(dx, L0 - dx);
    float dy = fabsf(A.y - B.y); dy = fminf(dy, L1 - dy);
    float dz = fabsf(A.z - B.z); dz = fminf(dz, L2 - dz);
    const float s = fmaf(dx, dx, fmaf(dy, dy, dz * dz));

    // d = sqrt(s) via rsqrt.approx + one Newton step (~1 ulp).
    // s == 0 (self pair) -> y=inf -> x=NaN -> d=NaN -> predicate false.
    float y; asm("rsqrt.approx.f32 %0, %1;" : "=f"(y) : "f"(s));
    const float x = s * y;
    const float d = x * fmaf(-0.5f * x, y, 1.5f);

    int k = (int)fmaf(d, inv_dx, kc);
    k = min(max(k, 0), nbm1);
    const float lo = bins_s[k];
    const float hi = bins_s[k + 1];
    k += (int)((hi <= d) & (k < nbm1));       // exact searchsorted fixup,
    k -= (int)((lo >  d) & (k > 0));          // mutually exclusive, branchless

    const int ok = (int)((d >= b0) & (d <= bN));
    const unsigned addr = hbase + ((unsigned)k << 2);
    asm volatile(
        "{\n\t.reg .pred p;\n\t"
        "setp.ne.s32 p, %0, 0;\n\t"
        "@p red.shared.add.u32 [%1], %2;\n\t}"
        :: "r"(ok), "r"(addr), "r"(w) : "memory");
}

// ---------------------------------------------------------------------------
// Per-(replica, pair-type, frame) histogram. blockIdx.x = (r*3+p)*T + t
// Symmetric types enumerate each unordered pair once (weight 2; weight 1 at
// the half-offset) -> counts bitwise equal to the full double-counted matrix.
// ---------------------------------------------------------------------------
__global__ __launch_bounds__(256) void hist_kernel(
    const float* __restrict__ radii,   // (T, R, N, 3)
    const float* __restrict__ lat,     // (3,)
    const float* __restrict__ bins,    // (nb+1,)
    int T, int R, int N, int nb)
{
    __shared__ float4 sO[NO];
    __shared__ float4 sH[NH];
    __shared__ float bins_s[NB_MAX + 1];
    __shared__ int hist[NB_MAX];

    const int bid = blockIdx.x;
    const int t  = bid % T;
    const int rp = bid / T;
    const int p  = rp % 3;
    const int r  = rp / 3;
    const int tid = threadIdx.x;

    const float L0 = lat[0], L1 = lat[1], L2 = lat[2];

    const float* base = radii + ((size_t)t * R + r) * (size_t)N * 3;
    for (int i = tid; i < NO; i += 256) {
        const int g = g_idxO[i];
        float f0 = base[3 * g    ] / L0;
        float f1 = base[3 * g + 1] / L1;
        float f2 = base[3 * g + 2] / L2;
        sO[i] = make_float4((f0 - floorf(f0)) * L0, (f1 - floorf(f1)) * L1,
                            (f2 - floorf(f2)) * L2, 0.0f);
    }
    for (int i = tid; i < NH; i += 256) {
        const int g = g_idxH[i];
        float f0 = base[3 * g    ] / L0;
        float f1 = base[3 * g + 1] / L1;
        float f2 = base[3 * g + 2] / L2;
        sH[i] = make_float4((f0 - floorf(f0)) * L0, (f1 - floorf(f1)) * L1,
                            (f2 - floorf(f2)) * L2, 0.0f);
    }
    for (int i = tid; i <= nb; i += 256) bins_s[i] = bins[i];
    for (int i = tid; i < nb; i += 256) hist[i] = 0;
    __syncthreads();

    const float b0 = bins_s[0], bN = bins_s[nb];
    const float inv_dx = (float)nb / (bN - b0);
    const float kc = -b0 * inv_dx;
    const int nbm1 = nb - 1;
    const unsigned hbase = (unsigned)__cvta_generic_to_shared(hist);

    if (p < 2) {
        const float4* arr = (p == 0) ? sO : sH;
        const int n    = (p == 0) ? NO : NH;
        const int step = 256 / n;
        const int j    = tid & (n - 1);
        const int c0   = tid / n;
        const int half = n >> 1;
        const float4 B = arr[j];
        #pragma unroll 4
        for (int o = 1 + c0; o <= half; o += step) {
            const int i = (j + o) & (n - 1);
            const int w = (o == half) ? 1 : 2;
            do_pair(arr[i], B, L0, L1, L2, b0, bN, inv_dx, kc, nbm1,
                    bins_s, hbase, w);
        }
    } else {
        const int j  = tid & (NO - 1);
        const int c0 = tid >> 6;
        const float4 B = sO[j];
        #pragma unroll 4
        for (int i = c0; i < NH; i += 4) {
            do_pair(sH[i], B, L0, L1, L2, b0, bN, inv_dx, kc, nbm1,
                    bins_s, hbase, 1);
        }
    }
    __syncthreads();

    float* gh = g_hists + ((size_t)rp * T + t) * nb;
    for (int i = tid; i < nb; i += 256) gh[i] = (float)hist[i];
}

// ---------------------------------------------------------------------------
// Per-(replica, pair-type) normalization + rdf + MAE; last finished block
// (monotonic counter) computes the per-replica max of the 3 MAEs.
// rdf[b] = (S/T) * sum_t h[t,b] * inv_shell[b] * (1/u_t),
// u_t = sum_b h[t,b]*inv_shell[b],  S = (vol/(T*P)) * sum_t u_t
// ---------------------------------------------------------------------------
__global__ __launch_bounds__(256) void reduce_kernel(
    const float* __restrict__ lat,
    const float* __restrict__ gt_oo,
    const float* __restrict__ gt_hh,
    const float* __restrict__ gt_ho,
    float* __restrict__ out,
    int T, int nb, int R)
{
    __shared__ float invsh[NB_MAX];
    __shared__ float u[128];
    __shared__ float red[256];
    __shared__ int sdone;

    const int rp = blockIdx.x;
    const int p = rp % 3;
    const int r = rp / 3;
    const int tid = threadIdx.x;

    for (int b = tid; b < nb; b += 256) invsh[b] = g_inv_shell[b];
    __syncthreads();

    const float* H = g_hists + (size_t)rp * T * nb;

    // per-frame weights u_t (deterministic serial per frame)
    if (tid < 128) u[tid] = 0.0f;
    __syncthreads();
    if (tid < T) {
        float acc = 0.0f;
        const float* row = H + (size_t)tid * nb;
        #pragma unroll 4
        for (int b = 0; b < nb; b++) acc = fmaf(row[b], invsh[b], acc);
        u[tid] = acc;
    }
    __syncthreads();

    // sum_t u_t  ->  S
    red[tid] = (tid < 128) ? u[tid] : 0.0f;
    __syncthreads();
    for (int s = 128; s > 0; s >>= 1) {
        if (tid < s) red[tid] += red[tid + s];
        __syncthreads();
    }
    const float sumU = red[0];
    __syncthreads();
    if (tid < T) u[tid] = 1.0f / u[tid];
    __syncthreads();

    const float vol = lat[0] * lat[1] * lat[2];
    const int P = (p == 0) ? NO * NO : (p == 1) ? NH * NH : NH * NO;
    const float SinvT = vol / ((float)T * (float)P) * sumU / (float)T;
    const float* gt = (p == 0) ? gt_oo : (p == 1) ? gt_hh : gt_ho;

    float* ro = out + ((size_t)r * 3 + p) * nb;
    float myabs = 0.0f;
    for (int b = tid; b < nb; b += 256) {
        float num = 0.0f;
        #pragma unroll 4
        for (int t = 0; t < T; t++)
            num = fmaf(H[(size_t)t * nb + b], u[t], num);
        const float rdf = SinvT * num * invsh[b];
        ro[b] = rdf;
        myabs += fabsf(rdf - gt[b]);
    }
    red[tid] = myabs;
    __syncthreads();
    for (int s = 128; s > 0; s >>= 1) {
        if (tid < s) red[tid] += red[tid + s];
        __syncthreads();
    }
    if (tid == 0) {
        g_maes[rp] = 6.0f * red[0] / (float)nb;   // XLIM * mean
        __threadfence();
        unsigned old = atomicAdd(&g_cnt, 1u);
        sdone = (int)(((old + 1u) % (unsigned)(3 * R)) == 0u);
    }
    __syncthreads();
    if (sdone) {
        __threadfence();
        if (tid < R) {
            volatile float* gm = g_maes;
            float m = gm[tid * 3];
            m = fmaxf(m, gm[tid * 3 + 1]);
            m = fmaxf(m, gm[tid * 3 + 2]);
            out[(size_t)R * 3 * nb + tid] = m;
        }
    }
}

// ---------------------------------------------------------------------------
extern "C" void kernel_launch(void* const* d_in, const int* in_sizes, int n_in,
                              void* d_out, int out_size) {
    const float* radii  = (const float*)d_in[0];   // (T,R,N,3)
    const int*   ptypes = (const int*)d_in[1];     // (N,)
    const float* lat    = (const float*)d_in[2];   // (3,)
    const float* bins   = (const float*)d_in[3];   // (nb+1,)
    const float* gt_oo  = (const float*)d_in[4];
    const float* gt_hh  = (const float*)d_in[5];
    const float* gt_ho  = (const float*)d_in[6];
    float* out = (float*)d_out;

    const int nb = in_sizes[3] - 1;                 // 600
    const int N  = in_sizes[1];                     // 192
    const int R  = out_size / (3 * nb + 1);         // 8
    const int T  = in_sizes[0] / (R * N * 3);       // 100

    init_kernel<<<1, 256>>>(ptypes, bins, N, nb);
    hist_kernel<<<R * 3 * T, 256>>>(radii, lat, bins, T, R, N, nb);
    reduce_kernel<<<R * 3, 256>>>(lat, gt_oo, gt_hh, gt_ho, out, T, nb, R);
}